// round 13
// baseline (speedup 1.0000x reference)
#include <cuda_runtime.h>
#include <cuda_bf16.h>
#include <cub/cub.cuh>
#include <math.h>

#define FHh 100
#define FWw 160
#define NPIX 16000
#define CIN 512
#define NANCH 144000
#define PRE 6000
#define POST 300
#define SCORES_OFF 0
#define REG_OFF 144000
#define PROP_OFF 720000
#define CUB_TEMP_CAP (1 << 24)
#define NCHUNK 144   // 9 taps x 16 ic-chunks of 32
#define APAD 36      // Abuf row stride in floats (144B: 16B-aligned)
#define WBUF_B 16384          // one W buffer: 32ic x 128oc x 4B
#define ABUF_B 4608           // one A buffer: 32px x 36 x 4B
#define SMEM_DYN (3 * (WBUF_B + ABUF_B))   // 62976B, triple buffered

// ---------------- static device scratch (no allocations allowed) ----------------
__device__ __align__(256) float g_y[NPIX * CIN];        // relu(conv1) output, NHWC
__device__ __align__(256) float g_wf[CIN * 64];          // fused 1x1 weights [ic][64]
__device__ float g_bf[64];                               // fused bias
__device__ __align__(256) unsigned g_keys_in[NANCH];
__device__ __align__(256) unsigned g_vals_in[NANCH];
__device__ __align__(256) unsigned g_keys_out[NANCH];
__device__ __align__(256) unsigned g_vals_out[NANCH];
__device__ __align__(256) unsigned char g_cub_temp[CUB_TEMP_CAP];
__device__ __align__(256) float4 g_boxes[PRE];
__device__ int g_valid[PRE];

// ---------------- asm helpers ----------------
__device__ __forceinline__ unsigned smem_u32(const void* p) {
    unsigned a;
    asm("{ .reg .u64 t; cvta.to.shared.u64 t, %1; cvt.u32.u64 %0, t; }" : "=r"(a) : "l"(p));
    return a;
}
#define CPA16(dst, src, sz) \
    asm volatile("cp.async.cg.shared.global [%0], [%1], 16, %2;" \
                 :: "r"(dst), "l"(src), "r"(sz) : "memory")
#define CPA_COMMIT() asm volatile("cp.async.commit_group;" ::: "memory")
#define CPA_WAIT1() asm volatile("cp.async.wait_group 1;" ::: "memory")
#define CPA_WAIT0() asm volatile("cp.async.wait_group 0;" ::: "memory")

// ---------------- profiling alignment dummies ----------------
__global__ void dummy_kernel() {}

// ---------------- pack fused 1x1 weights ----------------
__global__ void pack_kernel(const float* __restrict__ Wc, const float* __restrict__ bc,
                            const float* __restrict__ Wr, const float* __restrict__ br) {
    int i = blockIdx.x * blockDim.x + threadIdx.x;
    if (i < CIN * 64) {
        int ic = i >> 6, o = i & 63;
        float v = 0.f;
        if (o < 9)       v = Wc[ic * 9 + o];
        else if (o < 45) v = Wr[ic * 36 + (o - 9)];
        g_wf[i] = v;
    }
    if (i < 64) {
        float v = 0.f;
        if (i < 9)       v = bc[i];
        else if (i < 45) v = br[i - 9];
        g_bf[i] = v;
    }
}

// ---------------- 3x3 conv 512->512 + bias + relu (fp32, R1-identical numerics) ----------------
// block: 32 pixels x 128 oc (2000 CTAs: finer wave quantization), 256 threads,
// thread = 2px x 8oc (16 accums). Triple-buffered cp.async, one sync per chunk.
__global__ __launch_bounds__(256, 3)
void conv3x3_kernel(const float* __restrict__ F, const float* __restrict__ W1,
                    const float* __restrict__ b1) {
    extern __shared__ __align__(16) char sm[];
    // layout: [Wbuf0][Wbuf1][Wbuf2][Abuf0][Abuf1][Abuf2]
    const int tid = threadIdx.x;
    const int pg = tid >> 4;          // 0..15 (2 px each)
    const int ocg = tid & 15;         // 0..15
    const int pbase = blockIdx.x * 32;
    const int ocblk = blockIdx.y * 128;
    const int oc = ocblk + ocg * 8;

    // staging roles
    const int ap = tid >> 3;          // 0..31 pixel for act staging
    const int ag = tid & 7;           // 16B-quad within 32-ic row
    const int apy = (pbase + ap) / FWw;
    const int apx = (pbase + ap) % FWw;
    const int wr = tid >> 4;          // ic row (handles rows wr, wr+16)
    const int wc4 = (tid & 15) * 2;   // float4 col (2 consecutive)

    const unsigned wbase = smem_u32(sm);
    const unsigned abase = wbase + 3 * WBUF_B;
    unsigned a_sdst[3], w_sdst[3];
#pragma unroll
    for (int b = 0; b < 3; b++) {
        a_sdst[b] = abase + b * ABUF_B + ap * (APAD * 4) + ag * 16;
        w_sdst[b] = wbase + b * WBUF_B + (wr * 32 + wc4) * 16;
    }

    float acc[2][8];
#pragma unroll
    for (int k = 0; k < 2; k++)
#pragma unroll
        for (int j = 0; j < 8; j++) acc[k][j] = 0.f;

    // ---- stage chunk c (32 ic) into buffer b ----
    auto stage = [&](int c, int b) {
        const int tap = c >> 4;
        const int icc = c & 15;
        const int ic0 = icc * 32;
        const int dy = tap / 3 - 1, dx = tap % 3 - 1;
        // activations: one 16B vector per thread (zero-filled at SAME-padding)
        const int yy = apy + dy, xx = apx + dx;
        const bool v = ((unsigned)yy < (unsigned)FHh) && ((unsigned)xx < (unsigned)FWw);
        const float* asrc = F + ((size_t)(v ? (yy * FWw + xx) : 0) * CIN + ic0 + ag * 4);
        CPA16(a_sdst[b], asrc, v ? 16u : 0u);
        // weights: rows (ic0+wr) and (ic0+wr+16), two 16B vectors each
        const float* wsrc0 = W1 + (size_t)tap * CIN * CIN + (size_t)(ic0 + wr) * CIN + ocblk + wc4 * 4;
        const float* wsrc1 = wsrc0 + (size_t)16 * CIN;
        CPA16(w_sdst[b], wsrc0, 16u);
        CPA16(w_sdst[b] + 16, wsrc0 + 4, 16u);
        CPA16(w_sdst[b] + 16 * 512, wsrc1, 16u);
        CPA16(w_sdst[b] + 16 * 512 + 16, wsrc1 + 4, 16u);
    };

    stage(0, 0); CPA_COMMIT();
    stage(1, 1); CPA_COMMIT();

    for (int c = 0; c < NCHUNK; c++) {
        if (c < NCHUNK - 1) { CPA_WAIT1(); } else { CPA_WAIT0(); }
        __syncthreads();   // publish chunk c; orders compute(c-1) before stage(c+2)
        if (c + 2 < NCHUNK) {
            stage(c + 2, (c + 2) % 3);
            CPA_COMMIT();
        }

        const int buf = c % 3;
        const float* A = (const float*)(sm + 3 * WBUF_B + buf * ABUF_B);
        const float4* W = (const float4*)(sm + buf * WBUF_B);
#pragma unroll
        for (int i = 0; i < 32; i++) {
            float av[2];
            av[0] = A[(pg * 2 + 0) * APAD + i];
            av[1] = A[(pg * 2 + 1) * APAD + i];
            float4 w0 = W[i * 32 + ocg * 2];
            float4 w1 = W[i * 32 + ocg * 2 + 1];
            float wv[8] = {w0.x, w0.y, w0.z, w0.w, w1.x, w1.y, w1.z, w1.w};
#pragma unroll
            for (int k = 0; k < 2; k++)
#pragma unroll
                for (int j = 0; j < 8; j++) acc[k][j] += av[k] * wv[j];
        }
    }

    // epilogue: +bias, relu, store
    float4 bv0 = *(const float4*)(b1 + oc);
    float4 bv1 = *(const float4*)(b1 + oc + 4);
    float bb[8] = {bv0.x, bv0.y, bv0.z, bv0.w, bv1.x, bv1.y, bv1.z, bv1.w};
#pragma unroll
    for (int k = 0; k < 2; k++) {
        int p = pbase + pg * 2 + k;
        float4 o0, o1;
        o0.x = fmaxf(acc[k][0] + bb[0], 0.f);
        o0.y = fmaxf(acc[k][1] + bb[1], 0.f);
        o0.z = fmaxf(acc[k][2] + bb[2], 0.f);
        o0.w = fmaxf(acc[k][3] + bb[3], 0.f);
        o1.x = fmaxf(acc[k][4] + bb[4], 0.f);
        o1.y = fmaxf(acc[k][5] + bb[5], 0.f);
        o1.z = fmaxf(acc[k][6] + bb[6], 0.f);
        o1.w = fmaxf(acc[k][7] + bb[7], 0.f);
        *(float4*)&g_y[(size_t)p * CIN + oc]     = o0;
        *(float4*)&g_y[(size_t)p * CIN + oc + 4] = o1;
    }
}

// ---------------- fused 1x1 heads: scores (sigmoid) + reg, emit sort keys ----------------
__global__ __launch_bounds__(256)
void head_kernel(float* __restrict__ out) {
    const int tid = threadIdx.x;
    const int pxi = blockIdx.x * 32 + (tid >> 3);
    const int grp = tid & 7;

    float acc[8];
#pragma unroll
    for (int j = 0; j < 8; j++) acc[j] = g_bf[grp * 8 + j];

    const float* yrow = g_y + (size_t)pxi * CIN;
    const float4* wf4 = (const float4*)g_wf;
#pragma unroll 4
    for (int ic = 0; ic < CIN; ic++) {
        float a = __ldg(yrow + ic);
        float4 w0 = __ldg(wf4 + ic * 16 + grp * 2);
        float4 w1 = __ldg(wf4 + ic * 16 + grp * 2 + 1);
        acc[0] += a * w0.x; acc[1] += a * w0.y; acc[2] += a * w0.z; acc[3] += a * w0.w;
        acc[4] += a * w1.x; acc[5] += a * w1.y; acc[6] += a * w1.z; acc[7] += a * w1.w;
    }

#pragma unroll
    for (int j = 0; j < 8; j++) {
        int o = grp * 8 + j;
        if (o < 9) {
            float s = 1.f / (1.f + expf(-acc[j]));
            int idx = pxi * 9 + o;
            out[SCORES_OFF + idx] = s;
            g_keys_in[idx] = __float_as_uint(s);  // positive floats: uint order == float order
            g_vals_in[idx] = (unsigned)idx;
        } else if (o < 45) {
            out[REG_OFF + pxi * 36 + (o - 9)] = acc[j];
        }
    }
}

// ---------------- decode + clip + min-size for the top-6000 ----------------
__global__ void decode_kernel(const float* __restrict__ AM, const float* __restrict__ out) {
    int r = blockIdx.x * blockDim.x + threadIdx.x;
    if (r >= PRE) return;
    int idx = (int)g_vals_out[r];
    float4 an = __ldg((const float4*)AM + idx);
    float4 dl = *(const float4*)(out + REG_OFF + (size_t)idx * 4);
    float ah = an.z - an.x, aw = an.w - an.y;
    float acy = an.x + 0.5f * ah, acx = an.y + 0.5f * aw;
    float cy = acy + dl.x * ah, cx = acx + dl.y * aw;
    float h = ah * expf(dl.z), w = aw * expf(dl.w);
    float y1 = fmaxf(cy - 0.5f * h, 0.f);
    float x1 = fmaxf(cx - 0.5f * w, 0.f);
    float y2 = fminf(cy + 0.5f * h, 1600.f);
    float x2 = fminf(cx + 0.5f * w, 2560.f);
    g_boxes[r] = make_float4(y1, x1, y2, x2);
    g_valid[r] = (((y2 - y1) >= 16.f) && ((x2 - x1) >= 16.f)) ? 1 : 0;
}

// ---------------- greedy NMS (== reference argmax/suppress scan), single block ----------------
__global__ __launch_bounds__(1024)
void nms_kernel(float* __restrict__ outp) {
    __shared__ unsigned char alive[PRE];
    __shared__ int s_found;
    __shared__ int s_ptr;
    __shared__ float4 s_box;

    const int tid = threadIdx.x;
    for (int i = tid; i < PRE; i += 1024) alive[i] = (unsigned char)g_valid[i];
    if (tid == 0) s_ptr = 0;
    __syncthreads();

    for (int slot = 0; slot < POST; slot++) {
        if (tid < 32) {
            int p = s_ptr;
            int found = -1;
            while (p < PRE) {
                int i = p + tid;
                bool a = (i < PRE) && alive[i];
                unsigned m = __ballot_sync(0xffffffffu, a);
                if (m) { found = p + __ffs(m) - 1; break; }
                p += 32;
            }
            if (tid == 0) {
                s_found = found;
                if (found >= 0) {
                    alive[found] = 0;
                    s_ptr = found + 1;
                    s_box = g_boxes[found];
                } else {
                    s_ptr = PRE;
                }
            }
        }
        __syncthreads();
        int f = s_found;
        if (f < 0) {
            for (int i = slot * 4 + tid; i < POST * 4; i += 1024) outp[i] = 0.f;
            return;
        }
        float4 b = s_box;
        if (tid == 0) {
            outp[slot * 4 + 0] = b.x;
            outp[slot * 4 + 1] = b.y;
            outp[slot * 4 + 2] = b.z;
            outp[slot * 4 + 3] = b.w;
        }
        float ba = fmaxf(b.z - b.x, 0.f) * fmaxf(b.w - b.y, 0.f);
        for (int i = f + 1 + tid; i < PRE; i += 1024) {
            if (alive[i]) {
                float4 c = __ldg((const float4*)g_boxes + i);
                float yy1 = fmaxf(b.x, c.x), xx1 = fmaxf(b.y, c.y);
                float yy2 = fminf(b.z, c.z), xx2 = fminf(b.w, c.w);
                float inter = fmaxf(yy2 - yy1, 0.f) * fmaxf(xx2 - xx1, 0.f);
                float ca = fmaxf(c.z - c.x, 0.f) * fmaxf(c.w - c.y, 0.f);
                float iou = inter / (ba + ca - inter + 1e-8f);
                if (iou > 0.7f) alive[i] = 0;
            }
        }
        __syncthreads();
    }
}

// ---------------- host launcher ----------------
extern "C" void kernel_launch(void* const* d_in, const int* in_sizes, int n_in,
                              void* d_out, int out_size) {
    const float* F  = (const float*)d_in[1];
    const float* AM = (const float*)d_in[2];
    const float* W1 = (const float*)d_in[4];
    const float* b1 = (const float*)d_in[5];
    const float* Wc = (const float*)d_in[6];
    const float* bc = (const float*)d_in[7];
    const float* Wr = (const float*)d_in[8];
    const float* br = (const float*)d_in[9];
    float* out = (float*)d_out;

    cudaFuncSetAttribute(conv3x3_kernel,
                         cudaFuncAttributeMaxDynamicSharedMemorySize, SMEM_DYN);

    pack_kernel<<<(CIN * 64 + 255) / 256, 256>>>(Wc, bc, Wr, br);
    dummy_kernel<<<1, 1>>>();
    dummy_kernel<<<1, 1>>>();
    conv3x3_kernel<<<dim3(500, 4), 256, SMEM_DYN>>>(F, W1, b1);  // ncu capture target
    head_kernel<<<500, 256>>>(out);

    // stable descending radix sort of (score-bits, index): matches lax.top_k order incl. ties
    void *kin, *kout, *vin, *vout, *tmp;
    cudaGetSymbolAddress(&kin, g_keys_in);
    cudaGetSymbolAddress(&kout, g_keys_out);
    cudaGetSymbolAddress(&vin, g_vals_in);
    cudaGetSymbolAddress(&vout, g_vals_out);
    cudaGetSymbolAddress(&tmp, g_cub_temp);
    size_t tb = 0;
    cub::DeviceRadixSort::SortPairsDescending(
        nullptr, tb, (const unsigned*)kin, (unsigned*)kout,
        (const unsigned*)vin, (unsigned*)vout, NANCH, 0, 32, (cudaStream_t)0);
    if (tb <= (size_t)CUB_TEMP_CAP) {
        cub::DeviceRadixSort::SortPairsDescending(
            tmp, tb, (const unsigned*)kin, (unsigned*)kout,
            (const unsigned*)vin, (unsigned*)vout, NANCH, 0, 32, (cudaStream_t)0);
    }

    decode_kernel<<<(PRE + 255) / 256, 256>>>(AM, out);
    nms_kernel<<<1, 1024>>>(out + PROP_OFF);
}

// round 14
// speedup vs baseline: 1.8921x; 1.8921x over previous
#include <cuda_runtime.h>
#include <cuda_bf16.h>
#include <cub/cub.cuh>
#include <math.h>

#define FHh 100
#define FWw 160
#define NPIX 16000
#define CIN 512
#define NANCH 144000
#define PRE 6000
#define POST 300
#define SCORES_OFF 0
#define REG_OFF 144000
#define PROP_OFF 720000
#define CUB_TEMP_CAP (1 << 24)
#define NCHUNK 144   // 9 taps x 16 ic-chunks of 32
#define APAD 36      // Abuf row stride in floats (144B: 16B-aligned)
#define WBUF_B 16384          // one W buffer: 32ic x 128oc x 4B
#define ABUF_B 9216           // one A buffer: 64px x 36 x 4B
#define SMEM_DYN (3 * (WBUF_B + ABUF_B))   // 76800B, triple buffered

// ---------------- static device scratch (no allocations allowed) ----------------
__device__ __align__(256) float g_y[NPIX * CIN];        // relu(conv1) output, NHWC
__device__ __align__(256) float g_wf[CIN * 64];          // fused 1x1 weights [ic][64]
__device__ float g_bf[64];                               // fused bias
__device__ __align__(256) unsigned g_keys_in[NANCH];
__device__ __align__(256) unsigned g_vals_in[NANCH];
__device__ __align__(256) unsigned g_keys_out[NANCH];
__device__ __align__(256) unsigned g_vals_out[NANCH];
__device__ __align__(256) unsigned char g_cub_temp[CUB_TEMP_CAP];
__device__ __align__(256) float4 g_boxes[PRE];
__device__ int g_valid[PRE];

// ---------------- asm helpers ----------------
__device__ __forceinline__ unsigned smem_u32(const void* p) {
    unsigned a;
    asm("{ .reg .u64 t; cvta.to.shared.u64 t, %1; cvt.u32.u64 %0, t; }" : "=r"(a) : "l"(p));
    return a;
}
#define CPA16(dst, src, sz) \
    asm volatile("cp.async.cg.shared.global [%0], [%1], 16, %2;" \
                 :: "r"(dst), "l"(src), "r"(sz) : "memory")
#define CPA_COMMIT() asm volatile("cp.async.commit_group;" ::: "memory")
#define CPA_WAIT1() asm volatile("cp.async.wait_group 1;" ::: "memory")
#define CPA_WAIT0() asm volatile("cp.async.wait_group 0;" ::: "memory")

// ---------------- profiling alignment dummies ----------------
__global__ void dummy_kernel() {}

// ---------------- pack fused 1x1 weights ----------------
__global__ void pack_kernel(const float* __restrict__ Wc, const float* __restrict__ bc,
                            const float* __restrict__ Wr, const float* __restrict__ br) {
    int i = blockIdx.x * blockDim.x + threadIdx.x;
    if (i < CIN * 64) {
        int ic = i >> 6, o = i & 63;
        float v = 0.f;
        if (o < 9)       v = Wc[ic * 9 + o];
        else if (o < 45) v = Wr[ic * 36 + (o - 9)];
        g_wf[i] = v;
    }
    if (i < 64) {
        float v = 0.f;
        if (i < 9)       v = bc[i];
        else if (i < 45) v = br[i - 9];
        g_bf[i] = v;
    }
}

// ---------------- 3x3 conv 512->512 + bias + relu (fp32, R1-identical numerics) ----------------
// block: 64 pixels x 128 oc, 256 threads, thread = 4px x 8oc (32 accums).
// W smem DST-permuted half-layout: global float4-col c -> idx wr*32 + (c&1)*16 + (c>>1).
//   cp.async global src pattern unchanged (contiguous 32B per thread);
//   compute LDS.128 now reads 256B contiguous per 16 lanes (2 wavefronts, pg-broadcast).
__global__ __launch_bounds__(256, 3)
void conv3x3_kernel(const float* __restrict__ F, const float* __restrict__ W1,
                    const float* __restrict__ b1) {
    extern __shared__ __align__(16) char sm[];
    // layout: [Wbuf0][Wbuf1][Wbuf2][Abuf0][Abuf1][Abuf2]
    const int tid = threadIdx.x;
    const int pg = tid >> 4;          // 0..15 (4 px each)
    const int ocg = tid & 15;         // 0..15
    const int pbase = blockIdx.x * 64;
    const int ocblk = blockIdx.y * 128;
    const int oc = ocblk + ocg * 8;

    // staging roles
    const int ap = tid >> 2;          // 0..63 pixel for act staging
    const int ag = tid & 3;           // quad for act staging
    const int apy = (pbase + ap) / FWw;
    const int apx = (pbase + ap) % FWw;
    const int wr = tid >> 4;          // ic row (handles rows wr, wr+16)
    const int wt = tid & 15;          // thread's float4-col pair: cols 2*wt, 2*wt+1

    const unsigned wbase = smem_u32(sm);
    const unsigned abase = wbase + 3 * WBUF_B;
    unsigned a_sdst[3], w_sdst[3];
#pragma unroll
    for (int b = 0; b < 3; b++) {
        a_sdst[b] = abase + b * ABUF_B + ap * (APAD * 4) + ag * 16;
        // global col 2*wt -> idx wr*32 + wt (half 0); col 2*wt+1 -> wr*32 + 16 + wt (half 1)
        w_sdst[b] = wbase + b * WBUF_B + (wr * 32 + wt) * 16;
    }

    float acc[4][8];
#pragma unroll
    for (int k = 0; k < 4; k++)
#pragma unroll
        for (int j = 0; j < 8; j++) acc[k][j] = 0.f;

    // ---- stage chunk c (32 ic) into buffer b ----
    auto stage = [&](int c, int b) {
        const int tap = c >> 4;
        const int icc = c & 15;
        const int ic0 = icc * 32;
        const int dy = tap / 3 - 1, dx = tap % 3 - 1;
        // activations: two 16B vectors per thread (zero-filled at SAME-padding)
        const int yy = apy + dy, xx = apx + dx;
        const bool v = ((unsigned)yy < (unsigned)FHh) && ((unsigned)xx < (unsigned)FWw);
        const float* asrc = F + ((size_t)(v ? (yy * FWw + xx) : 0) * CIN + ic0 + ag * 4);
        CPA16(a_sdst[b], asrc, v ? 16u : 0u);
        CPA16(a_sdst[b] + 64, asrc + 16, v ? 16u : 0u);
        // weights: rows (ic0+wr) and (ic0+wr+16); global src contiguous 32B per thread,
        // dst permuted: col 2wt -> +0, col 2wt+1 -> +256B (16 float4s later)
        const float* wsrc0 = W1 + (size_t)tap * CIN * CIN + (size_t)(ic0 + wr) * CIN + ocblk + wt * 8;
        const float* wsrc1 = wsrc0 + (size_t)16 * CIN;
        CPA16(w_sdst[b], wsrc0, 16u);
        CPA16(w_sdst[b] + 256, wsrc0 + 4, 16u);
        CPA16(w_sdst[b] + 16 * 512, wsrc1, 16u);
        CPA16(w_sdst[b] + 16 * 512 + 256, wsrc1 + 4, 16u);
    };

    stage(0, 0); CPA_COMMIT();
    stage(1, 1); CPA_COMMIT();

    for (int c = 0; c < NCHUNK; c++) {
        if (c < NCHUNK - 1) { CPA_WAIT1(); } else { CPA_WAIT0(); }
        __syncthreads();   // publish chunk c; orders compute(c-1) before stage(c+2)
        if (c + 2 < NCHUNK) {
            stage(c + 2, (c + 2) % 3);
            CPA_COMMIT();
        }

        const int buf = c % 3;
        const float* A = (const float*)(sm + 3 * WBUF_B + buf * ABUF_B);
        const float4* W = (const float4*)(sm + buf * WBUF_B);
#pragma unroll
        for (int i = 0; i < 32; i++) {
            float av[4];
            av[0] = A[(pg * 4 + 0) * APAD + i];
            av[1] = A[(pg * 4 + 1) * APAD + i];
            av[2] = A[(pg * 4 + 2) * APAD + i];
            av[3] = A[(pg * 4 + 3) * APAD + i];
            float4 w0 = W[i * 32 + ocg];        // oc ocg*8..+3  (half 0, coalesced)
            float4 w1 = W[i * 32 + 16 + ocg];   // oc ocg*8+4..+7 (half 1, coalesced)
            float wv[8] = {w0.x, w0.y, w0.z, w0.w, w1.x, w1.y, w1.z, w1.w};
#pragma unroll
            for (int k = 0; k < 4; k++)
#pragma unroll
                for (int j = 0; j < 8; j++) acc[k][j] += av[k] * wv[j];
        }
    }

    // epilogue: +bias, relu, store
    float4 bv0 = *(const float4*)(b1 + oc);
    float4 bv1 = *(const float4*)(b1 + oc + 4);
    float bb[8] = {bv0.x, bv0.y, bv0.z, bv0.w, bv1.x, bv1.y, bv1.z, bv1.w};
#pragma unroll
    for (int k = 0; k < 4; k++) {
        int p = pbase + pg * 4 + k;
        float4 o0, o1;
        o0.x = fmaxf(acc[k][0] + bb[0], 0.f);
        o0.y = fmaxf(acc[k][1] + bb[1], 0.f);
        o0.z = fmaxf(acc[k][2] + bb[2], 0.f);
        o0.w = fmaxf(acc[k][3] + bb[3], 0.f);
        o1.x = fmaxf(acc[k][4] + bb[4], 0.f);
        o1.y = fmaxf(acc[k][5] + bb[5], 0.f);
        o1.z = fmaxf(acc[k][6] + bb[6], 0.f);
        o1.w = fmaxf(acc[k][7] + bb[7], 0.f);
        *(float4*)&g_y[(size_t)p * CIN + oc]     = o0;
        *(float4*)&g_y[(size_t)p * CIN + oc + 4] = o1;
    }
}

// ---------------- fused 1x1 heads: scores (sigmoid) + reg, emit sort keys ----------------
__global__ __launch_bounds__(256)
void head_kernel(float* __restrict__ out) {
    const int tid = threadIdx.x;
    const int pxi = blockIdx.x * 32 + (tid >> 3);
    const int grp = tid & 7;

    float acc[8];
#pragma unroll
    for (int j = 0; j < 8; j++) acc[j] = g_bf[grp * 8 + j];

    const float* yrow = g_y + (size_t)pxi * CIN;
    const float4* wf4 = (const float4*)g_wf;
#pragma unroll 4
    for (int ic = 0; ic < CIN; ic++) {
        float a = __ldg(yrow + ic);
        float4 w0 = __ldg(wf4 + ic * 16 + grp * 2);
        float4 w1 = __ldg(wf4 + ic * 16 + grp * 2 + 1);
        acc[0] += a * w0.x; acc[1] += a * w0.y; acc[2] += a * w0.z; acc[3] += a * w0.w;
        acc[4] += a * w1.x; acc[5] += a * w1.y; acc[6] += a * w1.z; acc[7] += a * w1.w;
    }

#pragma unroll
    for (int j = 0; j < 8; j++) {
        int o = grp * 8 + j;
        if (o < 9) {
            float s = 1.f / (1.f + expf(-acc[j]));
            int idx = pxi * 9 + o;
            out[SCORES_OFF + idx] = s;
            g_keys_in[idx] = __float_as_uint(s);  // positive floats: uint order == float order
            g_vals_in[idx] = (unsigned)idx;
        } else if (o < 45) {
            out[REG_OFF + pxi * 36 + (o - 9)] = acc[j];
        }
    }
}

// ---------------- decode + clip + min-size for the top-6000 ----------------
__global__ void decode_kernel(const float* __restrict__ AM, const float* __restrict__ out) {
    int r = blockIdx.x * blockDim.x + threadIdx.x;
    if (r >= PRE) return;
    int idx = (int)g_vals_out[r];
    float4 an = __ldg((const float4*)AM + idx);
    float4 dl = *(const float4*)(out + REG_OFF + (size_t)idx * 4);
    float ah = an.z - an.x, aw = an.w - an.y;
    float acy = an.x + 0.5f * ah, acx = an.y + 0.5f * aw;
    float cy = acy + dl.x * ah, cx = acx + dl.y * aw;
    float h = ah * expf(dl.z), w = aw * expf(dl.w);
    float y1 = fmaxf(cy - 0.5f * h, 0.f);
    float x1 = fmaxf(cx - 0.5f * w, 0.f);
    float y2 = fminf(cy + 0.5f * h, 1600.f);
    float x2 = fminf(cx + 0.5f * w, 2560.f);
    g_boxes[r] = make_float4(y1, x1, y2, x2);
    g_valid[r] = (((y2 - y1) >= 16.f) && ((x2 - x1) >= 16.f)) ? 1 : 0;
}

// ---------------- greedy NMS (== reference argmax/suppress scan), single block ----------------
__global__ __launch_bounds__(1024)
void nms_kernel(float* __restrict__ outp) {
    __shared__ unsigned char alive[PRE];
    __shared__ int s_found;
    __shared__ int s_ptr;
    __shared__ float4 s_box;

    const int tid = threadIdx.x;
    for (int i = tid; i < PRE; i += 1024) alive[i] = (unsigned char)g_valid[i];
    if (tid == 0) s_ptr = 0;
    __syncthreads();

    for (int slot = 0; slot < POST; slot++) {
        if (tid < 32) {
            int p = s_ptr;
            int found = -1;
            while (p < PRE) {
                int i = p + tid;
                bool a = (i < PRE) && alive[i];
                unsigned m = __ballot_sync(0xffffffffu, a);
                if (m) { found = p + __ffs(m) - 1; break; }
                p += 32;
            }
            if (tid == 0) {
                s_found = found;
                if (found >= 0) {
                    alive[found] = 0;
                    s_ptr = found + 1;
                    s_box = g_boxes[found];
                } else {
                    s_ptr = PRE;
                }
            }
        }
        __syncthreads();
        int f = s_found;
        if (f < 0) {
            for (int i = slot * 4 + tid; i < POST * 4; i += 1024) outp[i] = 0.f;
            return;
        }
        float4 b = s_box;
        if (tid == 0) {
            outp[slot * 4 + 0] = b.x;
            outp[slot * 4 + 1] = b.y;
            outp[slot * 4 + 2] = b.z;
            outp[slot * 4 + 3] = b.w;
        }
        float ba = fmaxf(b.z - b.x, 0.f) * fmaxf(b.w - b.y, 0.f);
        for (int i = f + 1 + tid; i < PRE; i += 1024) {
            if (alive[i]) {
                float4 c = __ldg((const float4*)g_boxes + i);
                float yy1 = fmaxf(b.x, c.x), xx1 = fmaxf(b.y, c.y);
                float yy2 = fminf(b.z, c.z), xx2 = fminf(b.w, c.w);
                float inter = fmaxf(yy2 - yy1, 0.f) * fmaxf(xx2 - xx1, 0.f);
                float ca = fmaxf(c.z - c.x, 0.f) * fmaxf(c.w - c.y, 0.f);
                float iou = inter / (ba + ca - inter + 1e-8f);
                if (iou > 0.7f) alive[i] = 0;
            }
        }
        __syncthreads();
    }
}

// ---------------- host launcher ----------------
extern "C" void kernel_launch(void* const* d_in, const int* in_sizes, int n_in,
                              void* d_out, int out_size) {
    const float* F  = (const float*)d_in[1];
    const float* AM = (const float*)d_in[2];
    const float* W1 = (const float*)d_in[4];
    const float* b1 = (const float*)d_in[5];
    const float* Wc = (const float*)d_in[6];
    const float* bc = (const float*)d_in[7];
    const float* Wr = (const float*)d_in[8];
    const float* br = (const float*)d_in[9];
    float* out = (float*)d_out;

    cudaFuncSetAttribute(conv3x3_kernel,
                         cudaFuncAttributeMaxDynamicSharedMemorySize, SMEM_DYN);

    pack_kernel<<<(CIN * 64 + 255) / 256, 256>>>(Wc, bc, Wr, br);
    dummy_kernel<<<1, 1>>>();
    dummy_kernel<<<1, 1>>>();
    conv3x3_kernel<<<dim3(250, 4), 256, SMEM_DYN>>>(F, W1, b1);  // ncu capture target
    head_kernel<<<500, 256>>>(out);

    // stable descending radix sort of (score-bits, index): matches lax.top_k order incl. ties
    void *kin, *kout, *vin, *vout, *tmp;
    cudaGetSymbolAddress(&kin, g_keys_in);
    cudaGetSymbolAddress(&kout, g_keys_out);
    cudaGetSymbolAddress(&vin, g_vals_in);
    cudaGetSymbolAddress(&vout, g_vals_out);
    cudaGetSymbolAddress(&tmp, g_cub_temp);
    size_t tb = 0;
    cub::DeviceRadixSort::SortPairsDescending(
        nullptr, tb, (const unsigned*)kin, (unsigned*)kout,
        (const unsigned*)vin, (unsigned*)vout, NANCH, 0, 32, (cudaStream_t)0);
    if (tb <= (size_t)CUB_TEMP_CAP) {
        cub::DeviceRadixSort::SortPairsDescending(
            tmp, tb, (const unsigned*)kin, (unsigned*)kout,
            (const unsigned*)vin, (unsigned*)vout, NANCH, 0, 32, (cudaStream_t)0);
    }

    decode_kernel<<<(PRE + 255) / 256, 256>>>(AM, out);
    nms_kernel<<<1, 1024>>>(out + PROP_OFF);
}

// round 15
// speedup vs baseline: 1.9043x; 1.0065x over previous
#include <cuda_runtime.h>
#include <cuda_bf16.h>
#include <cub/cub.cuh>
#include <math.h>

#define FHh 100
#define FWw 160
#define NPIX 16000
#define CIN 512
#define NANCH 144000
#define PRE 6000
#define POST 300
#define SCORES_OFF 0
#define REG_OFF 144000
#define PROP_OFF 720000
#define CUB_TEMP_CAP (1 << 24)
#define NCHUNK 144   // 9 taps x 16 ic-chunks of 32
#define APAD 36      // Abuf row stride in floats (144B: 16B-aligned)
#define WBUF_B 16384          // one W buffer: 32ic x 128oc x 4B
#define ABUF_B 9216           // one A buffer: 64px x 36 x 4B
#define SMEM_DYN (3 * (WBUF_B + ABUF_B))   // 76800B, triple buffered

// ---------------- static device scratch (no allocations allowed) ----------------
__device__ __align__(256) float g_y[NPIX * CIN];        // relu(conv1) output, NHWC
__device__ __align__(256) float g_wf[CIN * 64];          // fused 1x1 weights [ic][64]
__device__ float g_bf[64];                               // fused bias
__device__ __align__(256) unsigned g_keys_in[NANCH];
__device__ __align__(256) unsigned g_vals_in[NANCH];
__device__ __align__(256) unsigned g_keys_out[NANCH];
__device__ __align__(256) unsigned g_vals_out[NANCH];
__device__ __align__(256) unsigned char g_cub_temp[CUB_TEMP_CAP];
__device__ __align__(256) float4 g_boxes[PRE];
__device__ int g_valid[PRE];

// ---------------- asm helpers ----------------
__device__ __forceinline__ unsigned smem_u32(const void* p) {
    unsigned a;
    asm("{ .reg .u64 t; cvta.to.shared.u64 t, %1; cvt.u32.u64 %0, t; }" : "=r"(a) : "l"(p));
    return a;
}
#define CPA16(dst, src, sz) \
    asm volatile("cp.async.cg.shared.global [%0], [%1], 16, %2;" \
                 :: "r"(dst), "l"(src), "r"(sz) : "memory")
#define CPA_COMMIT() asm volatile("cp.async.commit_group;" ::: "memory")
#define CPA_WAIT1() asm volatile("cp.async.wait_group 1;" ::: "memory")
#define CPA_WAIT0() asm volatile("cp.async.wait_group 0;" ::: "memory")

// ---------------- profiling alignment dummies ----------------
__global__ void dummy_kernel() {}

// ---------------- pack fused 1x1 weights ----------------
__global__ void pack_kernel(const float* __restrict__ Wc, const float* __restrict__ bc,
                            const float* __restrict__ Wr, const float* __restrict__ br) {
    int i = blockIdx.x * blockDim.x + threadIdx.x;
    if (i < CIN * 64) {
        int ic = i >> 6, o = i & 63;
        float v = 0.f;
        if (o < 9)       v = Wc[ic * 9 + o];
        else if (o < 45) v = Wr[ic * 36 + (o - 9)];
        g_wf[i] = v;
    }
    if (i < 64) {
        float v = 0.f;
        if (i < 9)       v = bc[i];
        else if (i < 45) v = br[i - 9];
        g_bf[i] = v;
    }
}

// ---------------- 3x3 conv 512->512 + bias + relu (fp32, R1-identical numerics) ----------------
// block: 64 pixels x 128 oc, 256 threads, thread = 4px x 8oc (32 accums).
// W smem dst-permuted half-layout (coalesced LDS.128); A loads vectorized to
// float4 per 4 inner iters (accumulation order unchanged -> bit-identical).
__global__ __launch_bounds__(256, 2)
void conv3x3_kernel(const float* __restrict__ F, const float* __restrict__ W1,
                    const float* __restrict__ b1) {
    extern __shared__ __align__(16) char sm[];
    // layout: [Wbuf0][Wbuf1][Wbuf2][Abuf0][Abuf1][Abuf2]
    const int tid = threadIdx.x;
    const int pg = tid >> 4;          // 0..15 (4 px each)
    const int ocg = tid & 15;         // 0..15
    const int pbase = blockIdx.x * 64;
    const int ocblk = blockIdx.y * 128;
    const int oc = ocblk + ocg * 8;

    // staging roles
    const int ap = tid >> 2;          // 0..63 pixel for act staging
    const int ag = tid & 3;           // quad for act staging
    const int apy = (pbase + ap) / FWw;
    const int apx = (pbase + ap) % FWw;
    const int wr = tid >> 4;          // ic row (handles rows wr, wr+16)
    const int wt = tid & 15;          // thread's float4-col pair: cols 2*wt, 2*wt+1

    const unsigned wbase = smem_u32(sm);
    const unsigned abase = wbase + 3 * WBUF_B;
    unsigned a_sdst[3], w_sdst[3];
#pragma unroll
    for (int b = 0; b < 3; b++) {
        a_sdst[b] = abase + b * ABUF_B + ap * (APAD * 4) + ag * 16;
        // global col 2*wt -> idx wr*32 + wt (half 0); col 2*wt+1 -> wr*32 + 16 + wt (half 1)
        w_sdst[b] = wbase + b * WBUF_B + (wr * 32 + wt) * 16;
    }

    float acc[4][8];
#pragma unroll
    for (int k = 0; k < 4; k++)
#pragma unroll
        for (int j = 0; j < 8; j++) acc[k][j] = 0.f;

    // ---- stage chunk c (32 ic) into buffer b ----
    auto stage = [&](int c, int b) {
        const int tap = c >> 4;
        const int icc = c & 15;
        const int ic0 = icc * 32;
        const int dy = tap / 3 - 1, dx = tap % 3 - 1;
        // activations: two 16B vectors per thread (zero-filled at SAME-padding)
        const int yy = apy + dy, xx = apx + dx;
        const bool v = ((unsigned)yy < (unsigned)FHh) && ((unsigned)xx < (unsigned)FWw);
        const float* asrc = F + ((size_t)(v ? (yy * FWw + xx) : 0) * CIN + ic0 + ag * 4);
        CPA16(a_sdst[b], asrc, v ? 16u : 0u);
        CPA16(a_sdst[b] + 64, asrc + 16, v ? 16u : 0u);
        // weights: rows (ic0+wr) and (ic0+wr+16); global src contiguous 32B per thread,
        // dst permuted: col 2wt -> +0, col 2wt+1 -> +256B
        const float* wsrc0 = W1 + (size_t)tap * CIN * CIN + (size_t)(ic0 + wr) * CIN + ocblk + wt * 8;
        const float* wsrc1 = wsrc0 + (size_t)16 * CIN;
        CPA16(w_sdst[b], wsrc0, 16u);
        CPA16(w_sdst[b] + 256, wsrc0 + 4, 16u);
        CPA16(w_sdst[b] + 16 * 512, wsrc1, 16u);
        CPA16(w_sdst[b] + 16 * 512 + 256, wsrc1 + 4, 16u);
    };

    stage(0, 0); CPA_COMMIT();
    stage(1, 1); CPA_COMMIT();

    for (int c = 0; c < NCHUNK; c++) {
        if (c < NCHUNK - 1) { CPA_WAIT1(); } else { CPA_WAIT0(); }
        __syncthreads();   // publish chunk c; orders compute(c-1) before stage(c+2)
        if (c + 2 < NCHUNK) {
            stage(c + 2, (c + 2) % 3);
            CPA_COMMIT();
        }

        const int buf = c % 3;
        const float* A = (const float*)(sm + 3 * WBUF_B + buf * ABUF_B);
        const float4* W = (const float4*)(sm + buf * WBUF_B);
#pragma unroll
        for (int i4 = 0; i4 < 8; i4++) {
            float4 a4[4];
#pragma unroll
            for (int k = 0; k < 4; k++)
                a4[k] = *(const float4*)&A[(pg * 4 + k) * APAD + i4 * 4];
#pragma unroll
            for (int ii = 0; ii < 4; ii++) {
                const int i = i4 * 4 + ii;
                float4 w0 = W[i * 32 + ocg];        // oc ocg*8..+3  (half 0, coalesced)
                float4 w1 = W[i * 32 + 16 + ocg];   // oc ocg*8+4..+7 (half 1, coalesced)
                float wv[8] = {w0.x, w0.y, w0.z, w0.w, w1.x, w1.y, w1.z, w1.w};
                float av[4];
                av[0] = ((const float*)&a4[0])[ii];
                av[1] = ((const float*)&a4[1])[ii];
                av[2] = ((const float*)&a4[2])[ii];
                av[3] = ((const float*)&a4[3])[ii];
#pragma unroll
                for (int k = 0; k < 4; k++)
#pragma unroll
                    for (int j = 0; j < 8; j++) acc[k][j] += av[k] * wv[j];
            }
        }
    }

    // epilogue: +bias, relu, store
    float4 bv0 = *(const float4*)(b1 + oc);
    float4 bv1 = *(const float4*)(b1 + oc + 4);
    float bb[8] = {bv0.x, bv0.y, bv0.z, bv0.w, bv1.x, bv1.y, bv1.z, bv1.w};
#pragma unroll
    for (int k = 0; k < 4; k++) {
        int p = pbase + pg * 4 + k;
        float4 o0, o1;
        o0.x = fmaxf(acc[k][0] + bb[0], 0.f);
        o0.y = fmaxf(acc[k][1] + bb[1], 0.f);
        o0.z = fmaxf(acc[k][2] + bb[2], 0.f);
        o0.w = fmaxf(acc[k][3] + bb[3], 0.f);
        o1.x = fmaxf(acc[k][4] + bb[4], 0.f);
        o1.y = fmaxf(acc[k][5] + bb[5], 0.f);
        o1.z = fmaxf(acc[k][6] + bb[6], 0.f);
        o1.w = fmaxf(acc[k][7] + bb[7], 0.f);
        *(float4*)&g_y[(size_t)p * CIN + oc]     = o0;
        *(float4*)&g_y[(size_t)p * CIN + oc + 4] = o1;
    }
}

// ---------------- fused 1x1 heads: scores (sigmoid) + reg, emit sort keys ----------------
__global__ __launch_bounds__(256)
void head_kernel(float* __restrict__ out) {
    const int tid = threadIdx.x;
    const int pxi = blockIdx.x * 32 + (tid >> 3);
    const int grp = tid & 7;

    float acc[8];
#pragma unroll
    for (int j = 0; j < 8; j++) acc[j] = g_bf[grp * 8 + j];

    const float* yrow = g_y + (size_t)pxi * CIN;
    const float4* wf4 = (const float4*)g_wf;
#pragma unroll 4
    for (int ic = 0; ic < CIN; ic++) {
        float a = __ldg(yrow + ic);
        float4 w0 = __ldg(wf4 + ic * 16 + grp * 2);
        float4 w1 = __ldg(wf4 + ic * 16 + grp * 2 + 1);
        acc[0] += a * w0.x; acc[1] += a * w0.y; acc[2] += a * w0.z; acc[3] += a * w0.w;
        acc[4] += a * w1.x; acc[5] += a * w1.y; acc[6] += a * w1.z; acc[7] += a * w1.w;
    }

#pragma unroll
    for (int j = 0; j < 8; j++) {
        int o = grp * 8 + j;
        if (o < 9) {
            float s = 1.f / (1.f + expf(-acc[j]));
            int idx = pxi * 9 + o;
            out[SCORES_OFF + idx] = s;
            g_keys_in[idx] = __float_as_uint(s);  // positive floats: uint order == float order
            g_vals_in[idx] = (unsigned)idx;
        } else if (o < 45) {
            out[REG_OFF + pxi * 36 + (o - 9)] = acc[j];
        }
    }
}

// ---------------- decode + clip + min-size for the top-6000 ----------------
__global__ void decode_kernel(const float* __restrict__ AM, const float* __restrict__ out) {
    int r = blockIdx.x * blockDim.x + threadIdx.x;
    if (r >= PRE) return;
    int idx = (int)g_vals_out[r];
    float4 an = __ldg((const float4*)AM + idx);
    float4 dl = *(const float4*)(out + REG_OFF + (size_t)idx * 4);
    float ah = an.z - an.x, aw = an.w - an.y;
    float acy = an.x + 0.5f * ah, acx = an.y + 0.5f * aw;
    float cy = acy + dl.x * ah, cx = acx + dl.y * aw;
    float h = ah * expf(dl.z), w = aw * expf(dl.w);
    float y1 = fmaxf(cy - 0.5f * h, 0.f);
    float x1 = fmaxf(cx - 0.5f * w, 0.f);
    float y2 = fminf(cy + 0.5f * h, 1600.f);
    float x2 = fminf(cx + 0.5f * w, 2560.f);
    g_boxes[r] = make_float4(y1, x1, y2, x2);
    g_valid[r] = (((y2 - y1) >= 16.f) && ((x2 - x1) >= 16.f)) ? 1 : 0;
}

// ---------------- greedy NMS (== reference argmax/suppress scan), single block ----------------
__global__ __launch_bounds__(1024)
void nms_kernel(float* __restrict__ outp) {
    __shared__ unsigned char alive[PRE];
    __shared__ int s_found;
    __shared__ int s_ptr;
    __shared__ float4 s_box;

    const int tid = threadIdx.x;
    for (int i = tid; i < PRE; i += 1024) alive[i] = (unsigned char)g_valid[i];
    if (tid == 0) s_ptr = 0;
    __syncthreads();

    for (int slot = 0; slot < POST; slot++) {
        if (tid < 32) {
            int p = s_ptr;
            int found = -1;
            while (p < PRE) {
                int i = p + tid;
                bool a = (i < PRE) && alive[i];
                unsigned m = __ballot_sync(0xffffffffu, a);
                if (m) { found = p + __ffs(m) - 1; break; }
                p += 32;
            }
            if (tid == 0) {
                s_found = found;
                if (found >= 0) {
                    alive[found] = 0;
                    s_ptr = found + 1;
                    s_box = g_boxes[found];
                } else {
                    s_ptr = PRE;
                }
            }
        }
        __syncthreads();
        int f = s_found;
        if (f < 0) {
            for (int i = slot * 4 + tid; i < POST * 4; i += 1024) outp[i] = 0.f;
            return;
        }
        float4 b = s_box;
        if (tid == 0) {
            outp[slot * 4 + 0] = b.x;
            outp[slot * 4 + 1] = b.y;
            outp[slot * 4 + 2] = b.z;
            outp[slot * 4 + 3] = b.w;
        }
        float ba = fmaxf(b.z - b.x, 0.f) * fmaxf(b.w - b.y, 0.f);
        for (int i = f + 1 + tid; i < PRE; i += 1024) {
            if (alive[i]) {
                float4 c = __ldg((const float4*)g_boxes + i);
                float yy1 = fmaxf(b.x, c.x), xx1 = fmaxf(b.y, c.y);
                float yy2 = fminf(b.z, c.z), xx2 = fminf(b.w, c.w);
                float inter = fmaxf(yy2 - yy1, 0.f) * fmaxf(xx2 - xx1, 0.f);
                float ca = fmaxf(c.z - c.x, 0.f) * fmaxf(c.w - c.y, 0.f);
                float iou = inter / (ba + ca - inter + 1e-8f);
                if (iou > 0.7f) alive[i] = 0;
            }
        }
        __syncthreads();
    }
}

// ---------------- host launcher ----------------
extern "C" void kernel_launch(void* const* d_in, const int* in_sizes, int n_in,
                              void* d_out, int out_size) {
    const float* F  = (const float*)d_in[1];
    const float* AM = (const float*)d_in[2];
    const float* W1 = (const float*)d_in[4];
    const float* b1 = (const float*)d_in[5];
    const float* Wc = (const float*)d_in[6];
    const float* bc = (const float*)d_in[7];
    const float* Wr = (const float*)d_in[8];
    const float* br = (const float*)d_in[9];
    float* out = (float*)d_out;

    cudaFuncSetAttribute(conv3x3_kernel,
                         cudaFuncAttributeMaxDynamicSharedMemorySize, SMEM_DYN);

    pack_kernel<<<(CIN * 64 + 255) / 256, 256>>>(Wc, bc, Wr, br);
    dummy_kernel<<<1, 1>>>();
    dummy_kernel<<<1, 1>>>();
    conv3x3_kernel<<<dim3(250, 4), 256, SMEM_DYN>>>(F, W1, b1);  // ncu capture target
    head_kernel<<<500, 256>>>(out);

    // stable descending radix sort of (score-bits, index): matches lax.top_k order incl. ties
    void *kin, *kout, *vin, *vout, *tmp;
    cudaGetSymbolAddress(&kin, g_keys_in);
    cudaGetSymbolAddress(&kout, g_keys_out);
    cudaGetSymbolAddress(&vin, g_vals_in);
    cudaGetSymbolAddress(&vout, g_vals_out);
    cudaGetSymbolAddress(&tmp, g_cub_temp);
    size_t tb = 0;
    cub::DeviceRadixSort::SortPairsDescending(
        nullptr, tb, (const unsigned*)kin, (unsigned*)kout,
        (const unsigned*)vin, (unsigned*)vout, NANCH, 0, 32, (cudaStream_t)0);
    if (tb <= (size_t)CUB_TEMP_CAP) {
        cub::DeviceRadixSort::SortPairsDescending(
            tmp, tb, (const unsigned*)kin, (unsigned*)kout,
            (const unsigned*)vin, (unsigned*)vout, NANCH, 0, 32, (cudaStream_t)0);
    }

    decode_kernel<<<(PRE + 255) / 256, 256>>>(AM, out);
    nms_kernel<<<1, 1024>>>(out + PROP_OFF);
}

// round 16
// speedup vs baseline: 1.9084x; 1.0022x over previous
#include <cuda_runtime.h>
#include <cuda_bf16.h>
#include <cub/cub.cuh>
#include <math.h>

#define FHh 100
#define FWw 160
#define NPIX 16000
#define CIN 512
#define NANCH 144000
#define PRE 6000
#define POST 300
#define SCORES_OFF 0
#define REG_OFF 144000
#define PROP_OFF 720000
#define CUB_TEMP_CAP (1 << 24)
#define NCHUNK 144   // 9 taps x 16 ic-chunks of 32
#define APAD 36      // Abuf row stride in floats (144B: 16B-aligned)
#define WBUF_B 16384          // one W buffer: 32ic x 128oc x 4B
#define ABUF_B 9216           // one A buffer: 64px x 36 x 4B
#define SMEM_DYN (3 * (WBUF_B + ABUF_B))   // 76800B, triple buffered

// ---------------- static device scratch (no allocations allowed) ----------------
__device__ __align__(256) float g_y[NPIX * CIN];        // relu(conv1) output, NHWC
__device__ __align__(256) float g_wf[CIN * 64];          // fused 1x1 weights [ic][64]
__device__ float g_bf[64];                               // fused bias
__device__ __align__(256) unsigned g_keys_in[NANCH];
__device__ __align__(256) unsigned g_vals_in[NANCH];
__device__ __align__(256) unsigned g_keys_out[NANCH];
__device__ __align__(256) unsigned g_vals_out[NANCH];
__device__ __align__(256) unsigned char g_cub_temp[CUB_TEMP_CAP];
__device__ __align__(256) float4 g_boxes[PRE];
__device__ int g_valid[PRE];

// ---------------- asm helpers ----------------
__device__ __forceinline__ unsigned smem_u32(const void* p) {
    unsigned a;
    asm("{ .reg .u64 t; cvta.to.shared.u64 t, %1; cvt.u32.u64 %0, t; }" : "=r"(a) : "l"(p));
    return a;
}
#define CPA16(dst, src, sz) \
    asm volatile("cp.async.cg.shared.global [%0], [%1], 16, %2;" \
                 :: "r"(dst), "l"(src), "r"(sz) : "memory")
#define CPA_COMMIT() asm volatile("cp.async.commit_group;" ::: "memory")
#define CPA_WAIT1() asm volatile("cp.async.wait_group 1;" ::: "memory")
#define CPA_WAIT0() asm volatile("cp.async.wait_group 0;" ::: "memory")
// packed fp32x2 FMA: two independent rn-rounded fp32 FMAs (bit-identical to scalar chain)
#define FMA2(d, a, b) \
    asm("fma.rn.f32x2 %0, %1, %2, %0;" : "+l"(d) : "l"(a), "l"(b))
#define PACK_DUP(d, x) \
    asm("mov.b64 %0, {%1, %1};" : "=l"(d) : "r"(x))
#define UNPACK2(lo, hi, d) \
    asm("mov.b64 {%0, %1}, %2;" : "=f"(lo), "=f"(hi) : "l"(d))

// ---------------- profiling alignment dummies ----------------
__global__ void dummy_kernel() {}

// ---------------- pack fused 1x1 weights ----------------
__global__ void pack_kernel(const float* __restrict__ Wc, const float* __restrict__ bc,
                            const float* __restrict__ Wr, const float* __restrict__ br) {
    int i = blockIdx.x * blockDim.x + threadIdx.x;
    if (i < CIN * 64) {
        int ic = i >> 6, o = i & 63;
        float v = 0.f;
        if (o < 9)       v = Wc[ic * 9 + o];
        else if (o < 45) v = Wr[ic * 36 + (o - 9)];
        g_wf[i] = v;
    }
    if (i < 64) {
        float v = 0.f;
        if (i < 9)       v = bc[i];
        else if (i < 45) v = br[i - 9];
        g_bf[i] = v;
    }
}

// ---------------- 3x3 conv 512->512 + bias + relu (f32x2, R1-identical numerics) ----------------
// block: 64 pixels x 128 oc, 256 threads, thread = 4px x 8oc (16 f32x2 accums).
// W smem dst-permuted half-layout (coalesced LDS.128); float4 A loads; FFMA2 math.
__global__ __launch_bounds__(256, 2)
void conv3x3_kernel(const float* __restrict__ F, const float* __restrict__ W1,
                    const float* __restrict__ b1) {
    extern __shared__ __align__(16) char sm[];
    // layout: [Wbuf0][Wbuf1][Wbuf2][Abuf0][Abuf1][Abuf2]
    const int tid = threadIdx.x;
    const int pg = tid >> 4;          // 0..15 (4 px each)
    const int ocg = tid & 15;         // 0..15
    const int pbase = blockIdx.x * 64;
    const int ocblk = blockIdx.y * 128;
    const int oc = ocblk + ocg * 8;

    // staging roles
    const int ap = tid >> 2;          // 0..63 pixel for act staging
    const int ag = tid & 3;           // quad for act staging
    const int apy = (pbase + ap) / FWw;
    const int apx = (pbase + ap) % FWw;
    const int wr = tid >> 4;          // ic row (handles rows wr, wr+16)
    const int wt = tid & 15;          // thread's float4-col pair: cols 2*wt, 2*wt+1

    const unsigned wbase = smem_u32(sm);
    const unsigned abase = wbase + 3 * WBUF_B;
    unsigned a_sdst[3], w_sdst[3];
#pragma unroll
    for (int b = 0; b < 3; b++) {
        a_sdst[b] = abase + b * ABUF_B + ap * (APAD * 4) + ag * 16;
        // global col 2*wt -> idx wr*32 + wt (half 0); col 2*wt+1 -> wr*32 + 16 + wt (half 1)
        w_sdst[b] = wbase + b * WBUF_B + (wr * 32 + wt) * 16;
    }

    unsigned long long acc2[4][4];    // [px][oc-pair], each = 2 fp32 accums
#pragma unroll
    for (int k = 0; k < 4; k++)
#pragma unroll
        for (int j = 0; j < 4; j++) acc2[k][j] = 0ull;

    // ---- stage chunk c (32 ic) into buffer b ----
    auto stage = [&](int c, int b) {
        const int tap = c >> 4;
        const int icc = c & 15;
        const int ic0 = icc * 32;
        const int dy = tap / 3 - 1, dx = tap % 3 - 1;
        // activations: two 16B vectors per thread (zero-filled at SAME-padding)
        const int yy = apy + dy, xx = apx + dx;
        const bool v = ((unsigned)yy < (unsigned)FHh) && ((unsigned)xx < (unsigned)FWw);
        const float* asrc = F + ((size_t)(v ? (yy * FWw + xx) : 0) * CIN + ic0 + ag * 4);
        CPA16(a_sdst[b], asrc, v ? 16u : 0u);
        CPA16(a_sdst[b] + 64, asrc + 16, v ? 16u : 0u);
        // weights: rows (ic0+wr) and (ic0+wr+16); global src contiguous 32B per thread,
        // dst permuted: col 2wt -> +0, col 2wt+1 -> +256B
        const float* wsrc0 = W1 + (size_t)tap * CIN * CIN + (size_t)(ic0 + wr) * CIN + ocblk + wt * 8;
        const float* wsrc1 = wsrc0 + (size_t)16 * CIN;
        CPA16(w_sdst[b], wsrc0, 16u);
        CPA16(w_sdst[b] + 256, wsrc0 + 4, 16u);
        CPA16(w_sdst[b] + 16 * 512, wsrc1, 16u);
        CPA16(w_sdst[b] + 16 * 512 + 256, wsrc1 + 4, 16u);
    };

    stage(0, 0); CPA_COMMIT();
    stage(1, 1); CPA_COMMIT();

    for (int c = 0; c < NCHUNK; c++) {
        if (c < NCHUNK - 1) { CPA_WAIT1(); } else { CPA_WAIT0(); }
        __syncthreads();   // publish chunk c; orders compute(c-1) before stage(c+2)
        if (c + 2 < NCHUNK) {
            stage(c + 2, (c + 2) % 3);
            CPA_COMMIT();
        }

        const int buf = c % 3;
        const float* A = (const float*)(sm + 3 * WBUF_B + buf * ABUF_B);
        const ulonglong2* W2 = (const ulonglong2*)(sm + buf * WBUF_B);  // 16B units
#pragma unroll
        for (int i4 = 0; i4 < 8; i4++) {
            float4 a4[4];
#pragma unroll
            for (int k = 0; k < 4; k++)
                a4[k] = *(const float4*)&A[(pg * 4 + k) * APAD + i4 * 4];
#pragma unroll
            for (int ii = 0; ii < 4; ii++) {
                const int i = i4 * 4 + ii;
                ulonglong2 p0 = W2[i * 32 + ocg];        // oc ocg*8..+3  (half 0)
                ulonglong2 p1 = W2[i * 32 + 16 + ocg];   // oc ocg*8+4..+7 (half 1)
                unsigned long long wp[4] = {p0.x, p0.y, p1.x, p1.y};
                unsigned long long av2[4];
#pragma unroll
                for (int k = 0; k < 4; k++) {
                    float a = ((const float*)&a4[k])[ii];
                    PACK_DUP(av2[k], __float_as_uint(a));
                }
#pragma unroll
                for (int k = 0; k < 4; k++)
#pragma unroll
                    for (int j = 0; j < 4; j++)
                        FMA2(acc2[k][j], av2[k], wp[j]);
            }
        }
    }

    // epilogue: +bias, relu, store (same numerics as before)
    float4 bv0 = *(const float4*)(b1 + oc);
    float4 bv1 = *(const float4*)(b1 + oc + 4);
    float bb[8] = {bv0.x, bv0.y, bv0.z, bv0.w, bv1.x, bv1.y, bv1.z, bv1.w};
#pragma unroll
    for (int k = 0; k < 4; k++) {
        int p = pbase + pg * 4 + k;
        float a0, a1, a2, a3, a4v, a5, a6, a7;
        UNPACK2(a0, a1, acc2[k][0]);
        UNPACK2(a2, a3, acc2[k][1]);
        UNPACK2(a4v, a5, acc2[k][2]);
        UNPACK2(a6, a7, acc2[k][3]);
        float4 o0, o1;
        o0.x = fmaxf(a0 + bb[0], 0.f);
        o0.y = fmaxf(a1 + bb[1], 0.f);
        o0.z = fmaxf(a2 + bb[2], 0.f);
        o0.w = fmaxf(a3 + bb[3], 0.f);
        o1.x = fmaxf(a4v + bb[4], 0.f);
        o1.y = fmaxf(a5 + bb[5], 0.f);
        o1.z = fmaxf(a6 + bb[6], 0.f);
        o1.w = fmaxf(a7 + bb[7], 0.f);
        *(float4*)&g_y[(size_t)p * CIN + oc]     = o0;
        *(float4*)&g_y[(size_t)p * CIN + oc + 4] = o1;
    }
}

// ---------------- fused 1x1 heads: scores (sigmoid) + reg, emit sort keys ----------------
__global__ __launch_bounds__(256)
void head_kernel(float* __restrict__ out) {
    const int tid = threadIdx.x;
    const int pxi = blockIdx.x * 32 + (tid >> 3);
    const int grp = tid & 7;

    float acc[8];
#pragma unroll
    for (int j = 0; j < 8; j++) acc[j] = g_bf[grp * 8 + j];

    const float* yrow = g_y + (size_t)pxi * CIN;
    const float4* wf4 = (const float4*)g_wf;
#pragma unroll 4
    for (int ic = 0; ic < CIN; ic++) {
        float a = __ldg(yrow + ic);
        float4 w0 = __ldg(wf4 + ic * 16 + grp * 2);
        float4 w1 = __ldg(wf4 + ic * 16 + grp * 2 + 1);
        acc[0] += a * w0.x; acc[1] += a * w0.y; acc[2] += a * w0.z; acc[3] += a * w0.w;
        acc[4] += a * w1.x; acc[5] += a * w1.y; acc[6] += a * w1.z; acc[7] += a * w1.w;
    }

#pragma unroll
    for (int j = 0; j < 8; j++) {
        int o = grp * 8 + j;
        if (o < 9) {
            float s = 1.f / (1.f + expf(-acc[j]));
            int idx = pxi * 9 + o;
            out[SCORES_OFF + idx] = s;
            g_keys_in[idx] = __float_as_uint(s);  // positive floats: uint order == float order
            g_vals_in[idx] = (unsigned)idx;
        } else if (o < 45) {
            out[REG_OFF + pxi * 36 + (o - 9)] = acc[j];
        }
    }
}

// ---------------- decode + clip + min-size for the top-6000 ----------------
__global__ void decode_kernel(const float* __restrict__ AM, const float* __restrict__ out) {
    int r = blockIdx.x * blockDim.x + threadIdx.x;
    if (r >= PRE) return;
    int idx = (int)g_vals_out[r];
    float4 an = __ldg((const float4*)AM + idx);
    float4 dl = *(const float4*)(out + REG_OFF + (size_t)idx * 4);
    float ah = an.z - an.x, aw = an.w - an.y;
    float acy = an.x + 0.5f * ah, acx = an.y + 0.5f * aw;
    float cy = acy + dl.x * ah, cx = acx + dl.y * aw;
    float h = ah * expf(dl.z), w = aw * expf(dl.w);
    float y1 = fmaxf(cy - 0.5f * h, 0.f);
    float x1 = fmaxf(cx - 0.5f * w, 0.f);
    float y2 = fminf(cy + 0.5f * h, 1600.f);
    float x2 = fminf(cx + 0.5f * w, 2560.f);
    g_boxes[r] = make_float4(y1, x1, y2, x2);
    g_valid[r] = (((y2 - y1) >= 16.f) && ((x2 - x1) >= 16.f)) ? 1 : 0;
}

// ---------------- greedy NMS (== reference argmax/suppress scan), single block ----------------
__global__ __launch_bounds__(1024)
void nms_kernel(float* __restrict__ outp) {
    __shared__ unsigned char alive[PRE];
    __shared__ int s_found;
    __shared__ int s_ptr;
    __shared__ float4 s_box;

    const int tid = threadIdx.x;
    for (int i = tid; i < PRE; i += 1024) alive[i] = (unsigned char)g_valid[i];
    if (tid == 0) s_ptr = 0;
    __syncthreads();

    for (int slot = 0; slot < POST; slot++) {
        if (tid < 32) {
            int p = s_ptr;
            int found = -1;
            while (p < PRE) {
                int i = p + tid;
                bool a = (i < PRE) && alive[i];
                unsigned m = __ballot_sync(0xffffffffu, a);
                if (m) { found = p + __ffs(m) - 1; break; }
                p += 32;
            }
            if (tid == 0) {
                s_found = found;
                if (found >= 0) {
                    alive[found] = 0;
                    s_ptr = found + 1;
                    s_box = g_boxes[found];
                } else {
                    s_ptr = PRE;
                }
            }
        }
        __syncthreads();
        int f = s_found;
        if (f < 0) {
            for (int i = slot * 4 + tid; i < POST * 4; i += 1024) outp[i] = 0.f;
            return;
        }
        float4 b = s_box;
        if (tid == 0) {
            outp[slot * 4 + 0] = b.x;
            outp[slot * 4 + 1] = b.y;
            outp[slot * 4 + 2] = b.z;
            outp[slot * 4 + 3] = b.w;
        }
        float ba = fmaxf(b.z - b.x, 0.f) * fmaxf(b.w - b.y, 0.f);
        for (int i = f + 1 + tid; i < PRE; i += 1024) {
            if (alive[i]) {
                float4 c = __ldg((const float4*)g_boxes + i);
                float yy1 = fmaxf(b.x, c.x), xx1 = fmaxf(b.y, c.y);
                float yy2 = fminf(b.z, c.z), xx2 = fminf(b.w, c.w);
                float inter = fmaxf(yy2 - yy1, 0.f) * fmaxf(xx2 - xx1, 0.f);
                float ca = fmaxf(c.z - c.x, 0.f) * fmaxf(c.w - c.y, 0.f);
                float iou = inter / (ba + ca - inter + 1e-8f);
                if (iou > 0.7f) alive[i] = 0;
            }
        }
        __syncthreads();
    }
}

// ---------------- host launcher ----------------
extern "C" void kernel_launch(void* const* d_in, const int* in_sizes, int n_in,
                              void* d_out, int out_size) {
    const float* F  = (const float*)d_in[1];
    const float* AM = (const float*)d_in[2];
    const float* W1 = (const float*)d_in[4];
    const float* b1 = (const float*)d_in[5];
    const float* Wc = (const float*)d_in[6];
    const float* bc = (const float*)d_in[7];
    const float* Wr = (const float*)d_in[8];
    const float* br = (const float*)d_in[9];
    float* out = (float*)d_out;

    cudaFuncSetAttribute(conv3x3_kernel,
                         cudaFuncAttributeMaxDynamicSharedMemorySize, SMEM_DYN);

    pack_kernel<<<(CIN * 64 + 255) / 256, 256>>>(Wc, bc, Wr, br);
    dummy_kernel<<<1, 1>>>();
    dummy_kernel<<<1, 1>>>();
    conv3x3_kernel<<<dim3(250, 4), 256, SMEM_DYN>>>(F, W1, b1);  // ncu capture target
    head_kernel<<<500, 256>>>(out);

    // stable descending radix sort of (score-bits, index): matches lax.top_k order incl. ties
    void *kin, *kout, *vin, *vout, *tmp;
    cudaGetSymbolAddress(&kin, g_keys_in);
    cudaGetSymbolAddress(&kout, g_keys_out);
    cudaGetSymbolAddress(&vin, g_vals_in);
    cudaGetSymbolAddress(&vout, g_vals_out);
    cudaGetSymbolAddress(&tmp, g_cub_temp);
    size_t tb = 0;
    cub::DeviceRadixSort::SortPairsDescending(
        nullptr, tb, (const unsigned*)kin, (unsigned*)kout,
        (const unsigned*)vin, (unsigned*)vout, NANCH, 0, 32, (cudaStream_t)0);
    if (tb <= (size_t)CUB_TEMP_CAP) {
        cub::DeviceRadixSort::SortPairsDescending(
            tmp, tb, (const unsigned*)kin, (unsigned*)kout,
            (const unsigned*)vin, (unsigned*)vout, NANCH, 0, 32, (cudaStream_t)0);
    }

    decode_kernel<<<(PRE + 255) / 256, 256>>>(AM, out);
    nms_kernel<<<1, 1024>>>(out + PROP_OFF);
}